// round 1
// baseline (speedup 1.0000x reference)
#include <cuda_runtime.h>
#include <math.h>

#define EMBED 768
#define FF    3072
#define BATCH 8
#define SEQ   1024
#define TOK   (BATCH * SEQ)   // 8192

// ---------------- scratch (static device memory; no allocations) ------------
__device__ float g_Q[TOK * EMBED];
__device__ float g_Kp[TOK * EMBED];
__device__ float g_V[TOK * EMBED];
__device__ float g_S[(long)BATCH * SEQ * SEQ];   // 32 MB attention scores
__device__ float g_attn[TOK * EMBED];
__device__ float g_x1[TOK * EMBED];
__device__ float g_h[(long)TOK * FF];            // 100 MB FFN hidden
__device__ float g_f[TOK * EMBED];

// ---------------- SGEMM: 128x128 block tile, 8x8 per thread, K-tile 8 -------
// EPI: 0 = +bias, 1 = gelu(+bias), 2 = *scale (no bias)
// BT : false -> B stored [K,N] (NN);  true -> B stored [N,K] (NT, B^T)
__device__ __forceinline__ float gelu_exact(float v) {
    return 0.5f * v * (1.0f + erff(v * 0.7071067811865475f));
}

template <int EPI, bool BT>
__global__ __launch_bounds__(256, 2)
void sgemm_kernel(const float* __restrict__ A, const float* __restrict__ B,
                  const float* __restrict__ bias, float* __restrict__ C,
                  int M, int N, int K, float scale,
                  long sA, long sB, long sC)
{
    A += (long)blockIdx.z * sA;
    B += (long)blockIdx.z * sB;
    C += (long)blockIdx.z * sC;

    __shared__ float As[8][132];
    __shared__ float Bs[8][132];

    const int tid = threadIdx.x;
    const int tx  = tid & 15;          // 0..15 -> col group
    const int ty  = tid >> 4;          // 0..15 -> row group
    const int brow0 = blockIdx.y * 128;
    const int bcol0 = blockIdx.x * 128;

    // load mapping
    const int lrow = tid >> 1;         // 0..127
    const int lcol = (tid & 1) * 4;    // 0 or 4  (within K-tile)
    const int bKr  = tid >> 5;         // 0..7    (NN B row within K-tile)
    const int bNc  = (tid & 31) * 4;   // 0..124  (NN B col)

    float acc[8][8];
    #pragma unroll
    for (int i = 0; i < 8; i++)
        #pragma unroll
        for (int j = 0; j < 8; j++) acc[i][j] = 0.0f;

    const float* Aptr = A + (long)(brow0 + lrow) * K + lcol;

    for (int k0 = 0; k0 < K; k0 += 8) {
        // --- stage A tile (transposed into As[k][m]) ---
        float4 av = *(const float4*)(Aptr + k0);
        As[lcol + 0][lrow] = av.x;
        As[lcol + 1][lrow] = av.y;
        As[lcol + 2][lrow] = av.z;
        As[lcol + 3][lrow] = av.w;

        // --- stage B tile into Bs[k][n] ---
        if (BT) {
            float4 bv = *(const float4*)(B + (long)(bcol0 + lrow) * K + k0 + lcol);
            Bs[lcol + 0][lrow] = bv.x;
            Bs[lcol + 1][lrow] = bv.y;
            Bs[lcol + 2][lrow] = bv.z;
            Bs[lcol + 3][lrow] = bv.w;
        } else {
            float4 bv = *(const float4*)(B + (long)(k0 + bKr) * N + bcol0 + bNc);
            *(float4*)&Bs[bKr][bNc] = bv;
        }
        __syncthreads();

        #pragma unroll
        for (int k = 0; k < 8; k++) {
            float a[8], b[8];
            *(float4*)&a[0] = *(const float4*)&As[k][ty * 8];
            *(float4*)&a[4] = *(const float4*)&As[k][ty * 8 + 4];
            *(float4*)&b[0] = *(const float4*)&Bs[k][tx * 8];
            *(float4*)&b[4] = *(const float4*)&Bs[k][tx * 8 + 4];
            #pragma unroll
            for (int i = 0; i < 8; i++)
                #pragma unroll
                for (int j = 0; j < 8; j++)
                    acc[i][j] = fmaf(a[i], b[j], acc[i][j]);
        }
        __syncthreads();
    }

    // --- epilogue ---
    float bvals[8];
    if (EPI == 0 || EPI == 1) {
        #pragma unroll
        for (int j = 0; j < 8; j++) bvals[j] = bias[bcol0 + tx * 8 + j];
    }
    #pragma unroll
    for (int i = 0; i < 8; i++) {
        const int r = brow0 + ty * 8 + i;
        float* Crow = C + (long)r * N + bcol0 + tx * 8;
        float o[8];
        #pragma unroll
        for (int j = 0; j < 8; j++) {
            float v = acc[i][j];
            if (EPI == 0)      v += bvals[j];
            else if (EPI == 1) v = gelu_exact(v + bvals[j]);
            else               v *= scale;
            o[j] = v;
        }
        *(float4*)&Crow[0] = *(float4*)&o[0];
        *(float4*)&Crow[4] = *(float4*)&o[4];
    }
}

// ---------------- rowwise softmax over SEQ=1024 (one block per row) ---------
__global__ __launch_bounds__(256)
void softmax_kernel(float* __restrict__ S)
{
    float* row = S + (long)blockIdx.x * SEQ;
    const int tid = threadIdx.x;
    float v[4];
    float m = -1e30f;
    #pragma unroll
    for (int j = 0; j < 4; j++) { v[j] = row[tid + 256 * j]; m = fmaxf(m, v[j]); }

    __shared__ float red[8];
    #pragma unroll
    for (int o = 16; o > 0; o >>= 1) m = fmaxf(m, __shfl_xor_sync(0xffffffffu, m, o));
    if ((tid & 31) == 0) red[tid >> 5] = m;
    __syncthreads();
    m = red[0];
    #pragma unroll
    for (int i = 1; i < 8; i++) m = fmaxf(m, red[i]);

    float s = 0.0f;
    #pragma unroll
    for (int j = 0; j < 4; j++) { v[j] = expf(v[j] - m); s += v[j]; }
    __syncthreads();
    #pragma unroll
    for (int o = 16; o > 0; o >>= 1) s += __shfl_xor_sync(0xffffffffu, s, o);
    if ((tid & 31) == 0) red[tid >> 5] = s;
    __syncthreads();
    s = 0.0f;
    #pragma unroll
    for (int i = 0; i < 8; i++) s += red[i];
    const float inv = 1.0f / s;
    #pragma unroll
    for (int j = 0; j < 4; j++) row[tid + 256 * j] = v[j] * inv;
}

// ---------------- out = x + layernorm(t)*g + beta (row = 768) ---------------
__global__ __launch_bounds__(256)
void ln_residual_kernel(const float* __restrict__ xin, const float* __restrict__ t,
                        const float* __restrict__ g, const float* __restrict__ beta,
                        float* __restrict__ out)
{
    const long base = (long)blockIdx.x * EMBED;
    const int tid = threadIdx.x;
    float v0 = t[base + tid];
    float v1 = t[base + tid + 256];
    float v2 = t[base + tid + 512];
    float s = v0 + v1 + v2;
    float q = v0 * v0 + v1 * v1 + v2 * v2;

    __shared__ float rs[8], rq[8];
    #pragma unroll
    for (int o = 16; o > 0; o >>= 1) {
        s += __shfl_xor_sync(0xffffffffu, s, o);
        q += __shfl_xor_sync(0xffffffffu, q, o);
    }
    if ((tid & 31) == 0) { rs[tid >> 5] = s; rq[tid >> 5] = q; }
    __syncthreads();
    s = 0.0f; q = 0.0f;
    #pragma unroll
    for (int i = 0; i < 8; i++) { s += rs[i]; q += rq[i]; }

    const float mu  = s * (1.0f / EMBED);
    const float var = q * (1.0f / EMBED) - mu * mu;
    const float inv = rsqrtf(var + 1e-5f);

    out[base + tid]       = xin[base + tid]       + (v0 - mu) * inv * g[tid]       + beta[tid];
    out[base + tid + 256] = xin[base + tid + 256] + (v1 - mu) * inv * g[tid + 256] + beta[tid + 256];
    out[base + tid + 512] = xin[base + tid + 512] + (v2 - mu) * inv * g[tid + 512] + beta[tid + 512];
}

// ---------------- launch -----------------------------------------------------
extern "C" void kernel_launch(void* const* d_in, const int* in_sizes, int n_in,
                              void* d_out, int out_size)
{
    const float* x     = (const float*)d_in[0];
    const float* Wq    = (const float*)d_in[1];
    const float* bq    = (const float*)d_in[2];
    const float* Wk    = (const float*)d_in[3];
    const float* bk    = (const float*)d_in[4];
    const float* Wv    = (const float*)d_in[5];
    const float* bv    = (const float*)d_in[6];
    const float* W1    = (const float*)d_in[7];
    const float* b1    = (const float*)d_in[8];
    const float* W2    = (const float*)d_in[9];
    const float* b2    = (const float*)d_in[10];
    const float* g1    = (const float*)d_in[11];
    const float* beta1 = (const float*)d_in[12];
    const float* g2    = (const float*)d_in[13];
    const float* beta2 = (const float*)d_in[14];
    float* out = (float*)d_out;

    float *Q, *Kp, *V, *S, *attn, *x1, *h, *f;
    cudaGetSymbolAddress((void**)&Q,    g_Q);
    cudaGetSymbolAddress((void**)&Kp,   g_Kp);
    cudaGetSymbolAddress((void**)&V,    g_V);
    cudaGetSymbolAddress((void**)&S,    g_S);
    cudaGetSymbolAddress((void**)&attn, g_attn);
    cudaGetSymbolAddress((void**)&x1,   g_x1);
    cudaGetSymbolAddress((void**)&h,    g_h);
    cudaGetSymbolAddress((void**)&f,    g_f);

    const dim3 blk(256);
    const float att_scale = 1.0f / sqrtf((float)EMBED);

    // QKV projections: [8192,768] @ [768,768] + bias
    {
        dim3 grid(EMBED / 128, TOK / 128, 1);
        sgemm_kernel<0, false><<<grid, blk>>>(x, Wq, bq, Q,  TOK, EMBED, EMBED, 0.f, 0, 0, 0);
        sgemm_kernel<0, false><<<grid, blk>>>(x, Wk, bk, Kp, TOK, EMBED, EMBED, 0.f, 0, 0, 0);
        sgemm_kernel<0, false><<<grid, blk>>>(x, Wv, bv, V,  TOK, EMBED, EMBED, 0.f, 0, 0, 0);
    }
    // scores = Q @ K^T * scale   (per batch)
    {
        dim3 grid(SEQ / 128, SEQ / 128, BATCH);
        sgemm_kernel<2, true><<<grid, blk>>>(Q, Kp, nullptr, S, SEQ, SEQ, EMBED, att_scale,
                                             (long)SEQ * EMBED, (long)SEQ * EMBED, (long)SEQ * SEQ);
    }
    // softmax rows
    softmax_kernel<<<BATCH * SEQ, blk>>>(S);
    // attn_out = P @ V   (per batch)
    {
        dim3 grid(EMBED / 128, SEQ / 128, BATCH);
        sgemm_kernel<2, false><<<grid, blk>>>(S, V, nullptr, attn, SEQ, EMBED, SEQ, 1.0f,
                                              (long)SEQ * SEQ, (long)SEQ * EMBED, (long)SEQ * EMBED);
    }
    // x1 = x + LN(attn_out)
    ln_residual_kernel<<<TOK, blk>>>(x, attn, g1, beta1, x1);
    // h = gelu(x1 @ W1 + b1)
    {
        dim3 grid(FF / 128, TOK / 128, 1);
        sgemm_kernel<1, false><<<grid, blk>>>(x1, W1, b1, h, TOK, FF, EMBED, 0.f, 0, 0, 0);
    }
    // f = h @ W2 + b2
    {
        dim3 grid(EMBED / 128, TOK / 128, 1);
        sgemm_kernel<0, false><<<grid, blk>>>(h, W2, b2, f, TOK, EMBED, FF, 0.f, 0, 0, 0);
    }
    // out = x1 + LN(f)
    ln_residual_kernel<<<TOK, blk>>>(x1, f, g2, beta2, out);
}

// round 3
// speedup vs baseline: 2.9693x; 2.9693x over previous
#include <cuda_runtime.h>
#include <cuda_bf16.h>
#include <math.h>
#include <stdint.h>

#define EMBED 768
#define FF    3072
#define BATCH 8
#define SEQ   1024
#define TOK   (BATCH * SEQ)   // 8192

typedef __nv_bfloat16 bf16;

// ============================ scratch buffers ================================
__device__ __align__(16) bf16  g_xhi[TOK * EMBED],  g_xlo[TOK * EMBED];
__device__ __align__(16) bf16  g_WqTh[EMBED * EMBED], g_WqTl[EMBED * EMBED];
__device__ __align__(16) bf16  g_WkTh[EMBED * EMBED], g_WkTl[EMBED * EMBED];
__device__ __align__(16) bf16  g_WvTh[EMBED * EMBED], g_WvTl[EMBED * EMBED];
__device__ __align__(16) bf16  g_W1Th[(long)FF * EMBED], g_W1Tl[(long)FF * EMBED]; // [3072,768]
__device__ __align__(16) bf16  g_W2Th[(long)EMBED * FF], g_W2Tl[(long)EMBED * FF]; // [768,3072]
__device__ __align__(16) bf16  g_Qhi[TOK * EMBED], g_Qlo[TOK * EMBED];
__device__ __align__(16) bf16  g_Khi[TOK * EMBED], g_Klo[TOK * EMBED];
__device__ __align__(16) float g_Vf[TOK * EMBED];
__device__ __align__(16) bf16  g_VTh[(long)BATCH * EMBED * SEQ], g_VTl[(long)BATCH * EMBED * SEQ];
__device__ __align__(16) float g_S[(long)BATCH * SEQ * SEQ];
__device__ __align__(16) bf16  g_Phi[(long)BATCH * SEQ * SEQ], g_Plo[(long)BATCH * SEQ * SEQ];
__device__ __align__(16) float g_attn[TOK * EMBED];
__device__ __align__(16) float g_x1[TOK * EMBED];
__device__ __align__(16) bf16  g_x1hi[TOK * EMBED], g_x1lo[TOK * EMBED];
__device__ __align__(16) bf16  g_hhi[(long)TOK * FF], g_hlo[(long)TOK * FF];
__device__ __align__(16) float g_f[TOK * EMBED];

// ============================ PTX helpers ====================================
__device__ __forceinline__ uint32_t smem_u32(const void* p) {
    uint32_t a;
    asm("{ .reg .u64 t; cvta.to.shared.u64 t, %1; cvt.u32.u64 %0, t; }" : "=r"(a) : "l"(p));
    return a;
}

__device__ __forceinline__ void cp16(uint32_t dst, const void* src) {
    asm volatile("cp.async.cg.shared.global [%0], [%1], 16;" :: "r"(dst), "l"(src));
}
#define CP_COMMIT() asm volatile("cp.async.commit_group;" ::: "memory")

__device__ __forceinline__ void ldm_x4(uint32_t* r, uint32_t addr) {
    asm volatile("ldmatrix.sync.aligned.m8n8.x4.shared.b16 {%0,%1,%2,%3}, [%4];"
                 : "=r"(r[0]), "=r"(r[1]), "=r"(r[2]), "=r"(r[3]) : "r"(addr));
}

__device__ __forceinline__ void mma16816(float* d, const uint32_t* a, uint32_t b0, uint32_t b1) {
    asm volatile(
        "mma.sync.aligned.m16n8k16.row.col.f32.bf16.bf16.f32 "
        "{%0,%1,%2,%3}, {%4,%5,%6,%7}, {%8,%9}, {%0,%1,%2,%3};"
        : "+f"(d[0]), "+f"(d[1]), "+f"(d[2]), "+f"(d[3])
        : "r"(a[0]), "r"(a[1]), "r"(a[2]), "r"(a[3]), "r"(b0), "r"(b1));
}

#define SWZ128(o) ((o) ^ (((o) >> 3) & 0x70))

__device__ __forceinline__ float gelu_exact(float v) {
    return 0.5f * v * (1.0f + erff(v * 0.7071067811865475f));
}

// ============================ mma GEMM =======================================
// C[M,N] = (Ahi+Alo)[M,K] @ (Bhi+Blo)[N,K]^T   (both K-major row-major)
// CTA tile 128x128, BK=64, 3-stage cp.async pipe, 8 warps (warp tile 32x64).
// EPI: 0 bias->fp32 | 1 bias->(hi,lo) | 2 scale->fp32 | 3 bias+gelu->(hi,lo)
#define TILE_M 128
#define TILE_N 128
#define BK     64
#define STAGE_BYTES 65536              // Ah 16K | Al 16K | Bh 16K | Bl 16K
#define NSTAGE 3
#define GSMEM_TOTAL (NSTAGE * STAGE_BYTES)

template <int EPI>
__global__ __launch_bounds__(256, 1)
void mma_gemm(const bf16* __restrict__ Ahi, const bf16* __restrict__ Alo, long ldA, long bsA,
              const bf16* __restrict__ Bhi, const bf16* __restrict__ Blo, long ldB, long bsB,
              float* __restrict__ C, bf16* __restrict__ Chi, bf16* __restrict__ Clo,
              long ldC, long bsC, const float* __restrict__ bias, float scale, int K)
{
    extern __shared__ char smem[];
    const uint32_t sbase = smem_u32(smem);
    const int tid  = threadIdx.x;
    const int bz   = blockIdx.z;
    const int row0 = blockIdx.y * TILE_M;
    const int col0 = blockIdx.x * TILE_N;

    const bf16* Ah = Ahi + (long)bz * bsA;
    const bf16* Al = Alo + (long)bz * bsA;
    const bf16* Bh = Bhi + (long)bz * bsB;
    const bf16* Bl = Blo + (long)bz * bsB;

    // per-thread load slots: 4 chunks per 16KB tile (128 rows x 8 x 16B)
    const int lrow = (tid >> 3) & 127;            // reused via g = tid + 256*i
    (void)lrow;

    const int NC = K / BK;

    // ---- loader lambda-ish macro ----
    auto load_stage = [&](int buf, int k0) {
        const uint32_t sb = sbase + (uint32_t)buf * STAGE_BYTES;
        #pragma unroll
        for (int i = 0; i < 4; i++) {
            const int g = tid + 256 * i;          // 0..1023
            const int r = g >> 3;
            const int c = g & 7;
            const uint32_t off = SWZ128((uint32_t)(r * 128 + c * 16));
            const long ai = (long)(row0 + r) * ldA + k0 + c * 8;
            const long bi = (long)(col0 + r) * ldB + k0 + c * 8;
            cp16(sb + off,          Ah + ai);
            cp16(sb + 16384 + off,  Al + ai);
            cp16(sb + 32768 + off,  Bh + bi);
            cp16(sb + 49152 + off,  Bl + bi);
        }
    };

    load_stage(0, 0);
    CP_COMMIT();
    load_stage(1, BK);
    CP_COMMIT();

    const int w    = tid >> 5;
    const int lane = tid & 31;
    const int wm   = w & 3;            // M group: rows wm*32
    const int wn   = w >> 2;           // N group: cols wn*64
    const int q    = lane >> 3;
    const int r8   = lane & 7;

    float acc[2][8][4];
    #pragma unroll
    for (int i = 0; i < 2; i++)
        #pragma unroll
        for (int j = 0; j < 8; j++)
            #pragma unroll
            for (int v = 0; v < 4; v++) acc[i][j][v] = 0.0f;

    for (int c = 0; c < NC; c++) {
        if (c + 1 < NC) asm volatile("cp.async.wait_group 1;" ::: "memory");
        else            asm volatile("cp.async.wait_group 0;" ::: "memory");
        __syncthreads();
        if (c + 2 < NC) {
            load_stage((c + 2) % NSTAGE, (c + 2) * BK);
            CP_COMMIT();
        }

        const uint32_t sb = sbase + (uint32_t)(c % NSTAGE) * STAGE_BYTES;
        #pragma unroll
        for (int ks = 0; ks < 4; ks++) {
            uint32_t ah[2][4], al[2][4], bh[4][4], bl[4][4];
            // A frags: m-atom am -> rows wm*32 + am*16 + (q&1)*8 + r8, kchunk 2*ks + (q>>1)
            #pragma unroll
            for (int am = 0; am < 2; am++) {
                const int rr = wm * 32 + am * 16 + (q & 1) * 8 + r8;
                const int cc = 2 * ks + (q >> 1);
                const uint32_t off = SWZ128((uint32_t)(rr * 128 + cc * 16));
                ldm_x4(ah[am], sb + off);
                ldm_x4(al[am], sb + 16384 + off);
            }
            // B frags: pair p -> n = wn*64 + p*16 + (q>>1)*8 + r8, kchunk 2*ks + (q&1)
            #pragma unroll
            for (int p = 0; p < 4; p++) {
                const int nn = wn * 64 + p * 16 + (q >> 1) * 8 + r8;
                const int cc = 2 * ks + (q & 1);
                const uint32_t off = SWZ128((uint32_t)(nn * 128 + cc * 16));
                ldm_x4(bh[p], sb + 32768 + off);
                ldm_x4(bl[p], sb + 49152 + off);
            }
            // 3 passes into the same accumulators
            #pragma unroll
            for (int am = 0; am < 2; am++) {
                #pragma unroll
                for (int bn = 0; bn < 8; bn++) {
                    const int p = bn >> 1, hf = (bn & 1) * 2;
                    mma16816(acc[am][bn], ah[am], bh[p][hf], bh[p][hf + 1]);
                    mma16816(acc[am][bn], al[am], bh[p][hf], bh[p][hf + 1]);
                    mma16816(acc[am][bn], ah[am], bl[p][hf], bl[p][hf + 1]);
                }
            }
        }
        __syncthreads();
    }

    // -------- epilogue --------
    const int g = lane >> 2, t = lane & 3;
    float* Cp = (EPI == 0 || EPI == 2) ? C + (long)bz * bsC : nullptr;
    bf16* Hp  = (EPI == 1 || EPI == 3) ? Chi + (long)bz * bsC : nullptr;
    bf16* Lp  = (EPI == 1 || EPI == 3) ? Clo + (long)bz * bsC : nullptr;

    #pragma unroll
    for (int am = 0; am < 2; am++) {
        const long r0 = row0 + wm * 32 + am * 16 + g;
        const long r1 = r0 + 8;
        #pragma unroll
        for (int bn = 0; bn < 8; bn++) {
            const int col = col0 + wn * 64 + bn * 8 + 2 * t;
            float v[4];
            #pragma unroll
            for (int i = 0; i < 4; i++) v[i] = acc[am][bn][i];
            if (EPI == 2) {
                #pragma unroll
                for (int i = 0; i < 4; i++) v[i] *= scale;
            } else {
                const float b0 = __ldg(&bias[col]);
                const float b1 = __ldg(&bias[col + 1]);
                v[0] += b0; v[1] += b1; v[2] += b0; v[3] += b1;
                if (EPI == 3) {
                    #pragma unroll
                    for (int i = 0; i < 4; i++) v[i] = gelu_exact(v[i]);
                }
            }
            if (EPI == 0 || EPI == 2) {
                *(float2*)(Cp + r0 * ldC + col) = make_float2(v[0], v[1]);
                *(float2*)(Cp + r1 * ldC + col) = make_float2(v[2], v[3]);
            } else {
                ushort2 h0, h1, l0, l1;
                bf16 a0 = __float2bfloat16(v[0]), a1 = __float2bfloat16(v[1]);
                bf16 a2 = __float2bfloat16(v[2]), a3 = __float2bfloat16(v[3]);
                h0 = make_ushort2(__bfloat16_as_ushort(a0), __bfloat16_as_ushort(a1));
                h1 = make_ushort2(__bfloat16_as_ushort(a2), __bfloat16_as_ushort(a3));
                l0 = make_ushort2(
                    __bfloat16_as_ushort(__float2bfloat16(v[0] - __bfloat162float(a0))),
                    __bfloat16_as_ushort(__float2bfloat16(v[1] - __bfloat162float(a1))));
                l1 = make_ushort2(
                    __bfloat16_as_ushort(__float2bfloat16(v[2] - __bfloat162float(a2))),
                    __bfloat16_as_ushort(__float2bfloat16(v[3] - __bfloat162float(a3))));
                *(ushort2*)(Hp + r0 * ldC + col) = h0;
                *(ushort2*)(Hp + r1 * ldC + col) = h1;
                *(ushort2*)(Lp + r0 * ldC + col) = l0;
                *(ushort2*)(Lp + r1 * ldC + col) = l1;
            }
        }
    }
}

// ============================ glue kernels ===================================
__global__ __launch_bounds__(256)
void split_kernel(const float* __restrict__ in, bf16* __restrict__ hi, bf16* __restrict__ lo, long n4)
{
    long i = (long)blockIdx.x * blockDim.x + threadIdx.x;
    if (i >= n4) return;
    float4 v = ((const float4*)in)[i];
    unsigned short h[4], l[4];
    float vv[4] = {v.x, v.y, v.z, v.w};
    #pragma unroll
    for (int j = 0; j < 4; j++) {
        bf16 hb = __float2bfloat16(vv[j]);
        h[j] = __bfloat16_as_ushort(hb);
        l[j] = __bfloat16_as_ushort(__float2bfloat16(vv[j] - __bfloat162float(hb)));
    }
    ((uint2*)hi)[i] = *(uint2*)h;
    ((uint2*)lo)[i] = *(uint2*)l;
}

// in [B,R,C] fp32 -> out hi/lo [B,C,R] bf16
__global__ __launch_bounds__(256)
void split_transpose_kernel(const float* __restrict__ in, bf16* __restrict__ hi,
                            bf16* __restrict__ lo, int R, int C)
{
    __shared__ float t[32][33];
    const int tx = threadIdx.x, ty = threadIdx.y;
    const long bb = blockIdx.z;
    const float* ip = in + bb * (long)R * C;
    bf16* hp = hi + bb * (long)R * C;
    bf16* lp = lo + bb * (long)R * C;
    const int c = blockIdx.x * 32 + tx;
    const int r0 = blockIdx.y * 32;
    #pragma unroll
    for (int i = 0; i < 4; i++)
        t[ty + i * 8][tx] = ip[(long)(r0 + ty + i * 8) * C + c];
    __syncthreads();
    const int co0 = blockIdx.x * 32;
    #pragma unroll
    for (int i = 0; i < 4; i++) {
        float v = t[tx][ty + i * 8];
        bf16 h = __float2bfloat16(v);
        long o = (long)(co0 + ty + i * 8) * R + r0 + tx;
        hp[o] = h;
        lp[o] = __float2bfloat16(v - __bfloat162float(h));
    }
}

__global__ __launch_bounds__(256)
void softmax_kernel(float* __restrict__ S, bf16* __restrict__ Phi, bf16* __restrict__ Plo)
{
    float* row = S + (long)blockIdx.x * SEQ;
    const int tid = threadIdx.x;
    float v[4];
    float m = -1e30f;
    #pragma unroll
    for (int j = 0; j < 4; j++) { v[j] = row[tid + 256 * j]; m = fmaxf(m, v[j]); }
    __shared__ float red[8];
    #pragma unroll
    for (int o = 16; o > 0; o >>= 1) m = fmaxf(m, __shfl_xor_sync(0xffffffffu, m, o));
    if ((tid & 31) == 0) red[tid >> 5] = m;
    __syncthreads();
    m = red[0];
    #pragma unroll
    for (int i = 1; i < 8; i++) m = fmaxf(m, red[i]);
    float s = 0.0f;
    #pragma unroll
    for (int j = 0; j < 4; j++) { v[j] = expf(v[j] - m); s += v[j]; }
    __syncthreads();
    #pragma unroll
    for (int o = 16; o > 0; o >>= 1) s += __shfl_xor_sync(0xffffffffu, s, o);
    if ((tid & 31) == 0) red[tid >> 5] = s;
    __syncthreads();
    s = 0.0f;
    #pragma unroll
    for (int i = 0; i < 8; i++) s += red[i];
    const float inv = 1.0f / s;
    bf16* ph = Phi + (long)blockIdx.x * SEQ;
    bf16* pl = Plo + (long)blockIdx.x * SEQ;
    #pragma unroll
    for (int j = 0; j < 4; j++) {
        float p = v[j] * inv;
        bf16 h = __float2bfloat16(p);
        ph[tid + 256 * j] = h;
        pl[tid + 256 * j] = __float2bfloat16(p - __bfloat162float(h));
    }
}

template <bool SPLIT>
__global__ __launch_bounds__(256)
void ln_residual_kernel(const float* __restrict__ xin, const float* __restrict__ t,
                        const float* __restrict__ g, const float* __restrict__ beta,
                        float* __restrict__ out, bf16* __restrict__ ohi, bf16* __restrict__ olo)
{
    const long base = (long)blockIdx.x * EMBED;
    const int tid = threadIdx.x;
    float v0 = t[base + tid];
    float v1 = t[base + tid + 256];
    float v2 = t[base + tid + 512];
    float s = v0 + v1 + v2;
    float q = v0 * v0 + v1 * v1 + v2 * v2;
    __shared__ float rs[8], rq[8];
    #pragma unroll
    for (int o = 16; o > 0; o >>= 1) {
        s += __shfl_xor_sync(0xffffffffu, s, o);
        q += __shfl_xor_sync(0xffffffffu, q, o);
    }
    if ((tid & 31) == 0) { rs[tid >> 5] = s; rq[tid >> 5] = q; }
    __syncthreads();
    s = 0.0f; q = 0.0f;
    #pragma unroll
    for (int i = 0; i < 8; i++) { s += rs[i]; q += rq[i]; }
    const float mu  = s * (1.0f / EMBED);
    const float var = q * (1.0f / EMBED) - mu * mu;
    const float inv = rsqrtf(var + 1e-5f);
    #pragma unroll
    for (int j = 0; j < 3; j++) {
        const int o = tid + j * 256;
        const float vv = (j == 0 ? v0 : (j == 1 ? v1 : v2));
        float r = xin[base + o] + (vv - mu) * inv * g[o] + beta[o];
        out[base + o] = r;
        if (SPLIT) {
            bf16 h = __float2bfloat16(r);
            ohi[base + o] = h;
            olo[base + o] = __float2bfloat16(r - __bfloat162float(h));
        }
    }
}

// ============================ launcher =======================================
extern "C" void kernel_launch(void* const* d_in, const int* in_sizes, int n_in,
                              void* d_out, int out_size)
{
    const float* x     = (const float*)d_in[0];
    const float* Wq    = (const float*)d_in[1];
    const float* bq    = (const float*)d_in[2];
    const float* Wk    = (const float*)d_in[3];
    const float* bk    = (const float*)d_in[4];
    const float* Wv    = (const float*)d_in[5];
    const float* bv    = (const float*)d_in[6];
    const float* W1    = (const float*)d_in[7];
    const float* b1    = (const float*)d_in[8];
    const float* W2    = (const float*)d_in[9];
    const float* b2    = (const float*)d_in[10];
    const float* g1    = (const float*)d_in[11];
    const float* beta1 = (const float*)d_in[12];
    const float* g2    = (const float*)d_in[13];
    const float* beta2 = (const float*)d_in[14];
    float* out = (float*)d_out;

    bf16 *xhi, *xlo, *WqTh, *WqTl, *WkTh, *WkTl, *WvTh, *WvTl, *W1Th, *W1Tl, *W2Th, *W2Tl;
    bf16 *Qhi, *Qlo, *Khi, *Klo, *VTh, *VTl, *Phi, *Plo, *x1hi, *x1lo, *hhi, *hlo;
    float *Vf, *S, *attn, *x1, *f;
    cudaGetSymbolAddress((void**)&xhi, g_xhi);   cudaGetSymbolAddress((void**)&xlo, g_xlo);
    cudaGetSymbolAddress((void**)&WqTh, g_WqTh); cudaGetSymbolAddress((void**)&WqTl, g_WqTl);
    cudaGetSymbolAddress((void**)&WkTh, g_WkTh); cudaGetSymbolAddress((void**)&WkTl, g_WkTl);
    cudaGetSymbolAddress((void**)&WvTh, g_WvTh); cudaGetSymbolAddress((void**)&WvTl, g_WvTl);
    cudaGetSymbolAddress((void**)&W1Th, g_W1Th); cudaGetSymbolAddress((void**)&W1Tl, g_W1Tl);
    cudaGetSymbolAddress((void**)&W2Th, g_W2Th); cudaGetSymbolAddress((void**)&W2Tl, g_W2Tl);
    cudaGetSymbolAddress((void**)&Qhi, g_Qhi);   cudaGetSymbolAddress((void**)&Qlo, g_Qlo);
    cudaGetSymbolAddress((void**)&Khi, g_Khi);   cudaGetSymbolAddress((void**)&Klo, g_Klo);
    cudaGetSymbolAddress((void**)&Vf, g_Vf);
    cudaGetSymbolAddress((void**)&VTh, g_VTh);   cudaGetSymbolAddress((void**)&VTl, g_VTl);
    cudaGetSymbolAddress((void**)&S, g_S);
    cudaGetSymbolAddress((void**)&Phi, g_Phi);   cudaGetSymbolAddress((void**)&Plo, g_Plo);
    cudaGetSymbolAddress((void**)&attn, g_attn);
    cudaGetSymbolAddress((void**)&x1, g_x1);
    cudaGetSymbolAddress((void**)&x1hi, g_x1hi); cudaGetSymbolAddress((void**)&x1lo, g_x1lo);
    cudaGetSymbolAddress((void**)&hhi, g_hhi);   cudaGetSymbolAddress((void**)&hlo, g_hlo);
    cudaGetSymbolAddress((void**)&f, g_f);

    cudaFuncSetAttribute(mma_gemm<0>, cudaFuncAttributeMaxDynamicSharedMemorySize, GSMEM_TOTAL);
    cudaFuncSetAttribute(mma_gemm<1>, cudaFuncAttributeMaxDynamicSharedMemorySize, GSMEM_TOTAL);
    cudaFuncSetAttribute(mma_gemm<2>, cudaFuncAttributeMaxDynamicSharedMemorySize, GSMEM_TOTAL);
    cudaFuncSetAttribute(mma_gemm<3>, cudaFuncAttributeMaxDynamicSharedMemorySize, GSMEM_TOTAL);

    const dim3 blk(256);
    const dim3 tblk(32, 8);
    const float att_scale = 1.0f / sqrtf((float)EMBED);

    // input conversions
    split_kernel<<<(TOK * EMBED / 4 + 255) / 256, blk>>>(x, xhi, xlo, TOK * EMBED / 4);
    split_transpose_kernel<<<dim3(EMBED / 32, EMBED / 32, 1), tblk>>>(Wq, WqTh, WqTl, EMBED, EMBED);
    split_transpose_kernel<<<dim3(EMBED / 32, EMBED / 32, 1), tblk>>>(Wk, WkTh, WkTl, EMBED, EMBED);
    split_transpose_kernel<<<dim3(EMBED / 32, EMBED / 32, 1), tblk>>>(Wv, WvTh, WvTl, EMBED, EMBED);
    split_transpose_kernel<<<dim3(FF / 32, EMBED / 32, 1), tblk>>>(W1, W1Th, W1Tl, EMBED, FF);
    split_transpose_kernel<<<dim3(EMBED / 32, FF / 32, 1), tblk>>>(W2, W2Th, W2Tl, FF, EMBED);

    // Q, K projections -> bf16 hi/lo;  V -> fp32 (for transpose)
    mma_gemm<1><<<dim3(EMBED / TILE_N, TOK / TILE_M, 1), blk, GSMEM_TOTAL>>>(
        xhi, xlo, EMBED, 0, WqTh, WqTl, EMBED, 0, nullptr, Qhi, Qlo, EMBED, 0, bq, 0.f, EMBED);
    mma_gemm<1><<<dim3(EMBED / TILE_N, TOK / TILE_M, 1), blk, GSMEM_TOTAL>>>(
        xhi, xlo, EMBED, 0, WkTh, WkTl, EMBED, 0, nullptr, Khi, Klo, EMBED, 0, bk, 0.f, EMBED);
    mma_gemm<0><<<dim3(EMBED / TILE_N, TOK / TILE_M, 1), blk, GSMEM_TOTAL>>>(
        xhi, xlo, EMBED, 0, WvTh, WvTl, EMBED, 0, Vf, nullptr, nullptr, EMBED, 0, bv, 0.f, EMBED);
    split_transpose_kernel<<<dim3(EMBED / 32, SEQ / 32, BATCH), tblk>>>(Vf, VTh, VTl, SEQ, EMBED);

    // scores = Q @ K^T * scale  (batched)
    mma_gemm<2><<<dim3(SEQ / TILE_N, SEQ / TILE_M, BATCH), blk, GSMEM_TOTAL>>>(
        Qhi, Qlo, EMBED, (long)SEQ * EMBED, Khi, Klo, EMBED, (long)SEQ * EMBED,
        S, nullptr, nullptr, SEQ, (long)SEQ * SEQ, nullptr, att_scale, EMBED);
    softmax_kernel<<<TOK, blk>>>(S, Phi, Plo);
    // attn = P @ V  (batched, B = V^T)
    mma_gemm<2><<<dim3(EMBED / TILE_N, SEQ / TILE_M, BATCH), blk, GSMEM_TOTAL>>>(
        Phi, Plo, SEQ, (long)SEQ * SEQ, VTh, VTl, SEQ, (long)EMBED * SEQ,
        attn, nullptr, nullptr, EMBED, (long)SEQ * EMBED, nullptr, 1.0f, SEQ);

    // x1 = x + LN(attn)  (+ split for FFN)
    ln_residual_kernel<true><<<TOK, blk>>>(x, attn, g1, beta1, x1, x1hi, x1lo);

    // h = gelu(x1 @ W1 + b1) -> bf16 hi/lo
    mma_gemm<3><<<dim3(FF / TILE_N, TOK / TILE_M, 1), blk, GSMEM_TOTAL>>>(
        x1hi, x1lo, EMBED, 0, W1Th, W1Tl, EMBED, 0, nullptr, hhi, hlo, FF, 0, b1, 0.f, EMBED);
    // f = h @ W2 + b2
    mma_gemm<0><<<dim3(EMBED / TILE_N, TOK / TILE_M, 1), blk, GSMEM_TOTAL>>>(
        hhi, hlo, FF, 0, W2Th, W2Tl, FF, 0, f, nullptr, nullptr, EMBED, 0, b2, 0.f, FF);

    // out = x1 + LN(f)
    ln_residual_kernel<false><<<TOK, blk>>>(x1, f, g2, beta2, out, nullptr, nullptr);
}

// round 4
// speedup vs baseline: 3.0383x; 1.0232x over previous
#include <cuda_runtime.h>
#include <cuda_bf16.h>
#include <math.h>
#include <stdint.h>

#define EMBED 768
#define FF    3072
#define BATCH 8
#define SEQ   1024
#define TOK   (BATCH * SEQ)   // 8192
#define NQKV  (3 * EMBED)     // 2304

typedef __nv_bfloat16 bf16;

// ============================ scratch buffers ================================
__device__ __align__(16) bf16  g_xhi[TOK * EMBED],  g_xlo[TOK * EMBED];
__device__ __align__(16) bf16  g_Wqkvh[(long)NQKV * EMBED], g_Wqkvl[(long)NQKV * EMBED]; // [2304,768] K-major
__device__ __align__(16) float g_bqkv[NQKV];
__device__ __align__(16) bf16  g_W1Th[(long)FF * EMBED], g_W1Tl[(long)FF * EMBED];   // [3072,768]
__device__ __align__(16) bf16  g_W2Th[(long)EMBED * FF], g_W2Tl[(long)EMBED * FF];   // [768,3072]
__device__ __align__(16) bf16  g_QKVh[(long)TOK * NQKV], g_QKVl[(long)TOK * NQKV];   // fused Q|K|V
__device__ __align__(16) bf16  g_VTh[(long)BATCH * EMBED * SEQ], g_VTl[(long)BATCH * EMBED * SEQ];
__device__ __align__(16) float g_S[(long)BATCH * SEQ * SEQ];
__device__ __align__(16) bf16  g_Phi[(long)BATCH * SEQ * SEQ], g_Plo[(long)BATCH * SEQ * SEQ];
__device__ __align__(16) float g_attn[TOK * EMBED];
__device__ __align__(16) float g_x1[TOK * EMBED];
__device__ __align__(16) bf16  g_x1hi[TOK * EMBED], g_x1lo[TOK * EMBED];
__device__ __align__(16) bf16  g_hhi[(long)TOK * FF], g_hlo[(long)TOK * FF];
__device__ __align__(16) float g_f[TOK * EMBED];

// ============================ PTX helpers ====================================
__device__ __forceinline__ uint32_t smem_u32(const void* p) {
    uint32_t a;
    asm("{ .reg .u64 t; cvta.to.shared.u64 t, %1; cvt.u32.u64 %0, t; }" : "=r"(a) : "l"(p));
    return a;
}

__device__ __forceinline__ void cp16(uint32_t dst, const void* src) {
    asm volatile("cp.async.cg.shared.global [%0], [%1], 16;" :: "r"(dst), "l"(src));
}
#define CP_COMMIT() asm volatile("cp.async.commit_group;" ::: "memory")

__device__ __forceinline__ void ldm_x4(uint32_t* r, uint32_t addr) {
    asm volatile("ldmatrix.sync.aligned.m8n8.x4.shared.b16 {%0,%1,%2,%3}, [%4];"
                 : "=r"(r[0]), "=r"(r[1]), "=r"(r[2]), "=r"(r[3]) : "r"(addr));
}

__device__ __forceinline__ void mma16816(float* d, const uint32_t* a, uint32_t b0, uint32_t b1) {
    asm volatile(
        "mma.sync.aligned.m16n8k16.row.col.f32.bf16.bf16.f32 "
        "{%0,%1,%2,%3}, {%4,%5,%6,%7}, {%8,%9}, {%0,%1,%2,%3};"
        : "+f"(d[0]), "+f"(d[1]), "+f"(d[2]), "+f"(d[3])
        : "r"(a[0]), "r"(a[1]), "r"(a[2]), "r"(a[3]), "r"(b0), "r"(b1));
}

#define SWZ128(o) ((o) ^ (((o) >> 3) & 0x70))

__device__ __forceinline__ float gelu_exact(float v) {
    return 0.5f * v * (1.0f + erff(v * 0.7071067811865475f));
}

// ============================ mma GEMM =======================================
// C[M,N] = (Ahi+Alo)[M,K] @ (Bhi+Blo)[N,K]^T   (both K-major row-major)
// CTA tile 128x128, BK=64, 3-stage cp.async pipe, 8 warps (warp tile 32x64).
// EPI: 0 bias->fp32 | 1 bias->(hi,lo) | 2 scale->fp32 | 3 bias+gelu->(hi,lo)
#define TILE_M 128
#define TILE_N 128
#define BK     64
#define STAGE_BYTES 65536              // Ah 16K | Al 16K | Bh 16K | Bl 16K
#define NSTAGE 3
#define GSMEM_TOTAL (NSTAGE * STAGE_BYTES)

template <int EPI>
__global__ __launch_bounds__(256, 1)
void mma_gemm(const bf16* __restrict__ Ahi, const bf16* __restrict__ Alo, long ldA, long bsA,
              const bf16* __restrict__ Bhi, const bf16* __restrict__ Blo, long ldB, long bsB,
              float* __restrict__ C, bf16* __restrict__ Chi, bf16* __restrict__ Clo,
              long ldC, long bsC, const float* __restrict__ bias, float scale, int K)
{
    extern __shared__ char smem[];
    const uint32_t sbase = smem_u32(smem);
    const int tid  = threadIdx.x;
    const int bz   = blockIdx.z;
    const int row0 = blockIdx.y * TILE_M;
    const int col0 = blockIdx.x * TILE_N;

    const bf16* Ah = Ahi + (long)bz * bsA;
    const bf16* Al = Alo + (long)bz * bsA;
    const bf16* Bh = Bhi + (long)bz * bsB;
    const bf16* Bl = Blo + (long)bz * bsB;

    const int NC = K / BK;

    auto load_stage = [&](int buf, int k0) {
        const uint32_t sb = sbase + (uint32_t)buf * STAGE_BYTES;
        #pragma unroll
        for (int i = 0; i < 4; i++) {
            const int g = tid + 256 * i;          // 0..1023
            const int r = g >> 3;
            const int c = g & 7;
            const uint32_t off = SWZ128((uint32_t)(r * 128 + c * 16));
            const long ai = (long)(row0 + r) * ldA + k0 + c * 8;
            const long bi = (long)(col0 + r) * ldB + k0 + c * 8;
            cp16(sb + off,          Ah + ai);
            cp16(sb + 16384 + off,  Al + ai);
            cp16(sb + 32768 + off,  Bh + bi);
            cp16(sb + 49152 + off,  Bl + bi);
        }
    };

    load_stage(0, 0);
    CP_COMMIT();
    load_stage(1, BK);
    CP_COMMIT();

    const int w    = tid >> 5;
    const int lane = tid & 31;
    const int wm   = w & 3;            // M group: rows wm*32
    const int wn   = w >> 2;           // N group: cols wn*64
    const int q    = lane >> 3;
    const int r8   = lane & 7;

    float acc[2][8][4];
    #pragma unroll
    for (int i = 0; i < 2; i++)
        #pragma unroll
        for (int j = 0; j < 8; j++)
            #pragma unroll
            for (int v = 0; v < 4; v++) acc[i][j][v] = 0.0f;

    for (int c = 0; c < NC; c++) {
        if (c + 1 < NC) asm volatile("cp.async.wait_group 1;" ::: "memory");
        else            asm volatile("cp.async.wait_group 0;" ::: "memory");
        __syncthreads();
        if (c + 2 < NC) {
            load_stage((c + 2) % NSTAGE, (c + 2) * BK);
            CP_COMMIT();
        }

        const uint32_t sb = sbase + (uint32_t)(c % NSTAGE) * STAGE_BYTES;
        #pragma unroll
        for (int ks = 0; ks < 4; ks++) {
            uint32_t ah[2][4], al[2][4], bh[4][4], bl[4][4];
            #pragma unroll
            for (int am = 0; am < 2; am++) {
                const int rr = wm * 32 + am * 16 + (q & 1) * 8 + r8;
                const int cc = 2 * ks + (q >> 1);
                const uint32_t off = SWZ128((uint32_t)(rr * 128 + cc * 16));
                ldm_x4(ah[am], sb + off);
                ldm_x4(al[am], sb + 16384 + off);
            }
            #pragma unroll
            for (int p = 0; p < 4; p++) {
                const int nn = wn * 64 + p * 16 + (q >> 1) * 8 + r8;
                const int cc = 2 * ks + (q & 1);
                const uint32_t off = SWZ128((uint32_t)(nn * 128 + cc * 16));
                ldm_x4(bh[p], sb + 32768 + off);
                ldm_x4(bl[p], sb + 49152 + off);
            }
            #pragma unroll
            for (int am = 0; am < 2; am++) {
                #pragma unroll
                for (int bn = 0; bn < 8; bn++) {
                    const int p = bn >> 1, hf = (bn & 1) * 2;
                    mma16816(acc[am][bn], ah[am], bh[p][hf], bh[p][hf + 1]);
                    mma16816(acc[am][bn], al[am], bh[p][hf], bh[p][hf + 1]);
                    mma16816(acc[am][bn], ah[am], bl[p][hf], bl[p][hf + 1]);
                }
            }
        }
        __syncthreads();
    }

    // -------- epilogue --------
    const int g = lane >> 2, t = lane & 3;
    float* Cp = (EPI == 0 || EPI == 2) ? C + (long)bz * bsC : nullptr;
    bf16* Hp  = (EPI == 1 || EPI == 3) ? Chi + (long)bz * bsC : nullptr;
    bf16* Lp  = (EPI == 1 || EPI == 3) ? Clo + (long)bz * bsC : nullptr;

    #pragma unroll
    for (int am = 0; am < 2; am++) {
        const long r0 = row0 + wm * 32 + am * 16 + g;
        const long r1 = r0 + 8;
        #pragma unroll
        for (int bn = 0; bn < 8; bn++) {
            const int col = col0 + wn * 64 + bn * 8 + 2 * t;
            float v[4];
            #pragma unroll
            for (int i = 0; i < 4; i++) v[i] = acc[am][bn][i];
            if (EPI == 2) {
                #pragma unroll
                for (int i = 0; i < 4; i++) v[i] *= scale;
            } else {
                const float b0 = __ldg(&bias[col]);
                const float b1 = __ldg(&bias[col + 1]);
                v[0] += b0; v[1] += b1; v[2] += b0; v[3] += b1;
                if (EPI == 3) {
                    #pragma unroll
                    for (int i = 0; i < 4; i++) v[i] = gelu_exact(v[i]);
                }
            }
            if (EPI == 0 || EPI == 2) {
                *(float2*)(Cp + r0 * ldC + col) = make_float2(v[0], v[1]);
                *(float2*)(Cp + r1 * ldC + col) = make_float2(v[2], v[3]);
            } else {
                bf16 a0 = __float2bfloat16(v[0]), a1 = __float2bfloat16(v[1]);
                bf16 a2 = __float2bfloat16(v[2]), a3 = __float2bfloat16(v[3]);
                ushort2 h0 = make_ushort2(__bfloat16_as_ushort(a0), __bfloat16_as_ushort(a1));
                ushort2 h1 = make_ushort2(__bfloat16_as_ushort(a2), __bfloat16_as_ushort(a3));
                ushort2 l0 = make_ushort2(
                    __bfloat16_as_ushort(__float2bfloat16(v[0] - __bfloat162float(a0))),
                    __bfloat16_as_ushort(__float2bfloat16(v[1] - __bfloat162float(a1))));
                ushort2 l1 = make_ushort2(
                    __bfloat16_as_ushort(__float2bfloat16(v[2] - __bfloat162float(a2))),
                    __bfloat16_as_ushort(__float2bfloat16(v[3] - __bfloat162float(a3))));
                *(ushort2*)(Hp + r0 * ldC + col) = h0;
                *(ushort2*)(Hp + r1 * ldC + col) = h1;
                *(ushort2*)(Lp + r0 * ldC + col) = l0;
                *(ushort2*)(Lp + r1 * ldC + col) = l1;
            }
        }
    }
}

// ============================ glue kernels ===================================
__global__ __launch_bounds__(256)
void split_kernel(const float* __restrict__ in, bf16* __restrict__ hi, bf16* __restrict__ lo, long n4)
{
    long i = (long)blockIdx.x * blockDim.x + threadIdx.x;
    if (i >= n4) return;
    float4 v = ((const float4*)in)[i];
    unsigned short h[4], l[4];
    float vv[4] = {v.x, v.y, v.z, v.w};
    #pragma unroll
    for (int j = 0; j < 4; j++) {
        bf16 hb = __float2bfloat16(vv[j]);
        h[j] = __bfloat16_as_ushort(hb);
        l[j] = __bfloat16_as_ushort(__float2bfloat16(vv[j] - __bfloat162float(hb)));
    }
    ((uint2*)hi)[i] = *(uint2*)h;
    ((uint2*)lo)[i] = *(uint2*)l;
}

// in [R,C] fp32 -> out hi/lo [C,R] bf16 (weights)
__global__ __launch_bounds__(256)
void split_transpose_kernel(const float* __restrict__ in, bf16* __restrict__ hi,
                            bf16* __restrict__ lo, int R, int C)
{
    __shared__ float t[32][33];
    const int tx = threadIdx.x, ty = threadIdx.y;
    const int c = blockIdx.x * 32 + tx;
    const int r0 = blockIdx.y * 32;
    #pragma unroll
    for (int i = 0; i < 4; i++)
        t[ty + i * 8][tx] = in[(long)(r0 + ty + i * 8) * C + c];
    __syncthreads();
    const int co0 = blockIdx.x * 32;
    #pragma unroll
    for (int i = 0; i < 4; i++) {
        float v = t[tx][ty + i * 8];
        bf16 h = __float2bfloat16(v);
        long o = (long)(co0 + ty + i * 8) * R + r0 + tx;
        hi[o] = h;
        lo[o] = __float2bfloat16(v - __bfloat162float(h));
    }
}

__global__ void concat_bias_kernel(const float* __restrict__ bq, const float* __restrict__ bk,
                                   const float* __restrict__ bv, float* __restrict__ o)
{
    int i = blockIdx.x * blockDim.x + threadIdx.x;
    if (i >= NQKV) return;
    o[i] = (i < EMBED) ? bq[i] : (i < 2 * EMBED) ? bk[i - EMBED] : bv[i - 2 * EMBED];
}

// V slice of fused QKV (hi+lo, token-major, ld=NQKV) -> VT hi/lo [B, EMBED, SEQ]
__global__ __launch_bounds__(256)
void vt_transpose_kernel(const bf16* __restrict__ hi_in, const bf16* __restrict__ lo_in,
                         bf16* __restrict__ hiT, bf16* __restrict__ loT)
{
    __shared__ float t[32][33];
    const int tx = threadIdx.x, ty = threadIdx.y;
    const long b = blockIdx.z;
    const int e = blockIdx.x * 32 + tx;      // 0..767
    const int s0 = blockIdx.y * 32;
    const long ib = b * SEQ;
    #pragma unroll
    for (int i = 0; i < 4; i++) {
        const long idx = (ib + s0 + ty + i * 8) * NQKV + 2 * EMBED + e;
        t[ty + i * 8][tx] = __bfloat162float(hi_in[idx]) + __bfloat162float(lo_in[idx]);
    }
    __syncthreads();
    const int e0 = blockIdx.x * 32;
    #pragma unroll
    for (int i = 0; i < 4; i++) {
        float v = t[tx][ty + i * 8];
        bf16 h = __float2bfloat16(v);
        const long o = b * EMBED * SEQ + (long)(e0 + ty + i * 8) * SEQ + s0 + tx;
        hiT[o] = h;
        loT[o] = __float2bfloat16(v - __bfloat162float(h));
    }
}

__global__ __launch_bounds__(256)
void softmax_kernel(float* __restrict__ S, bf16* __restrict__ Phi, bf16* __restrict__ Plo)
{
    float* row = S + (long)blockIdx.x * SEQ;
    const int tid = threadIdx.x;
    float v[4];
    float m = -1e30f;
    #pragma unroll
    for (int j = 0; j < 4; j++) { v[j] = row[tid + 256 * j]; m = fmaxf(m, v[j]); }
    __shared__ float red[8];
    #pragma unroll
    for (int o = 16; o > 0; o >>= 1) m = fmaxf(m, __shfl_xor_sync(0xffffffffu, m, o));
    if ((tid & 31) == 0) red[tid >> 5] = m;
    __syncthreads();
    m = red[0];
    #pragma unroll
    for (int i = 1; i < 8; i++) m = fmaxf(m, red[i]);
    float s = 0.0f;
    #pragma unroll
    for (int j = 0; j < 4; j++) { v[j] = __expf(v[j] - m); s += v[j]; }
    __syncthreads();
    #pragma unroll
    for (int o = 16; o > 0; o >>= 1) s += __shfl_xor_sync(0xffffffffu, s, o);
    if ((tid & 31) == 0) red[tid >> 5] = s;
    __syncthreads();
    s = 0.0f;
    #pragma unroll
    for (int i = 0; i < 8; i++) s += red[i];
    const float inv = 1.0f / s;
    bf16* ph = Phi + (long)blockIdx.x * SEQ;
    bf16* pl = Plo + (long)blockIdx.x * SEQ;
    #pragma unroll
    for (int j = 0; j < 4; j++) {
        float p = v[j] * inv;
        bf16 h = __float2bfloat16(p);
        ph[tid + 256 * j] = h;
        pl[tid + 256 * j] = __float2bfloat16(p - __bfloat162float(h));
    }
}

template <bool SPLIT>
__global__ __launch_bounds__(256)
void ln_residual_kernel(const float* __restrict__ xin, const float* __restrict__ t,
                        const float* __restrict__ g, const float* __restrict__ beta,
                        float* __restrict__ out, bf16* __restrict__ ohi, bf16* __restrict__ olo)
{
    const long base = (long)blockIdx.x * EMBED;
    const int tid = threadIdx.x;
    float v0 = t[base + tid];
    float v1 = t[base + tid + 256];
    float v2 = t[base + tid + 512];
    float s = v0 + v1 + v2;
    float q = v0 * v0 + v1 * v1 + v2 * v2;
    __shared__ float rs[8], rq[8];
    #pragma unroll
    for (int o = 16; o > 0; o >>= 1) {
        s += __shfl_xor_sync(0xffffffffu, s, o);
        q += __shfl_xor_sync(0xffffffffu, q, o);
    }
    if ((tid & 31) == 0) { rs[tid >> 5] = s; rq[tid >> 5] = q; }
    __syncthreads();
    s = 0.0f; q = 0.0f;
    #pragma unroll
    for (int i = 0; i < 8; i++) { s += rs[i]; q += rq[i]; }
    const float mu  = s * (1.0f / EMBED);
    const float var = q * (1.0f / EMBED) - mu * mu;
    const float inv = rsqrtf(var + 1e-5f);
    #pragma unroll
    for (int j = 0; j < 3; j++) {
        const int o = tid + j * 256;
        const float vv = (j == 0 ? v0 : (j == 1 ? v1 : v2));
        float r = xin[base + o] + (vv - mu) * inv * g[o] + beta[o];
        out[base + o] = r;
        if (SPLIT) {
            bf16 h = __float2bfloat16(r);
            ohi[base + o] = h;
            olo[base + o] = __float2bfloat16(r - __bfloat162float(h));
        }
    }
}

// ============================ launcher =======================================
extern "C" void kernel_launch(void* const* d_in, const int* in_sizes, int n_in,
                              void* d_out, int out_size)
{
    const float* x     = (const float*)d_in[0];
    const float* Wq    = (const float*)d_in[1];
    const float* bq    = (const float*)d_in[2];
    const float* Wk    = (const float*)d_in[3];
    const float* bk    = (const float*)d_in[4];
    const float* Wv    = (const float*)d_in[5];
    const float* bv    = (const float*)d_in[6];
    const float* W1    = (const float*)d_in[7];
    const float* b1    = (const float*)d_in[8];
    const float* W2    = (const float*)d_in[9];
    const float* b2    = (const float*)d_in[10];
    const float* g1    = (const float*)d_in[11];
    const float* beta1 = (const float*)d_in[12];
    const float* g2    = (const float*)d_in[13];
    const float* beta2 = (const float*)d_in[14];
    float* out = (float*)d_out;

    bf16 *xhi, *xlo, *Wqkvh, *Wqkvl, *W1Th, *W1Tl, *W2Th, *W2Tl;
    bf16 *QKVh, *QKVl, *VTh, *VTl, *Phi, *Plo, *x1hi, *x1lo, *hhi, *hlo;
    float *bqkv, *S, *attn, *x1, *f;
    cudaGetSymbolAddress((void**)&xhi, g_xhi);     cudaGetSymbolAddress((void**)&xlo, g_xlo);
    cudaGetSymbolAddress((void**)&Wqkvh, g_Wqkvh); cudaGetSymbolAddress((void**)&Wqkvl, g_Wqkvl);
    cudaGetSymbolAddress((void**)&bqkv, g_bqkv);
    cudaGetSymbolAddress((void**)&W1Th, g_W1Th);   cudaGetSymbolAddress((void**)&W1Tl, g_W1Tl);
    cudaGetSymbolAddress((void**)&W2Th, g_W2Th);   cudaGetSymbolAddress((void**)&W2Tl, g_W2Tl);
    cudaGetSymbolAddress((void**)&QKVh, g_QKVh);   cudaGetSymbolAddress((void**)&QKVl, g_QKVl);
    cudaGetSymbolAddress((void**)&VTh, g_VTh);     cudaGetSymbolAddress((void**)&VTl, g_VTl);
    cudaGetSymbolAddress((void**)&S, g_S);
    cudaGetSymbolAddress((void**)&Phi, g_Phi);     cudaGetSymbolAddress((void**)&Plo, g_Plo);
    cudaGetSymbolAddress((void**)&attn, g_attn);
    cudaGetSymbolAddress((void**)&x1, g_x1);
    cudaGetSymbolAddress((void**)&x1hi, g_x1hi);   cudaGetSymbolAddress((void**)&x1lo, g_x1lo);
    cudaGetSymbolAddress((void**)&hhi, g_hhi);     cudaGetSymbolAddress((void**)&hlo, g_hlo);
    cudaGetSymbolAddress((void**)&f, g_f);

    cudaFuncSetAttribute(mma_gemm<0>, cudaFuncAttributeMaxDynamicSharedMemorySize, GSMEM_TOTAL);
    cudaFuncSetAttribute(mma_gemm<1>, cudaFuncAttributeMaxDynamicSharedMemorySize, GSMEM_TOTAL);
    cudaFuncSetAttribute(mma_gemm<2>, cudaFuncAttributeMaxDynamicSharedMemorySize, GSMEM_TOTAL);
    cudaFuncSetAttribute(mma_gemm<3>, cudaFuncAttributeMaxDynamicSharedMemorySize, GSMEM_TOTAL);

    const dim3 blk(256);
    const dim3 tblk(32, 8);
    const float att_scale = 1.0f / sqrtf((float)EMBED);

    // 1-5: conversions (launch #6 must be the fused QKV GEMM for ncu -s 5 -c 1)
    split_kernel<<<(TOK * EMBED / 4 + 255) / 256, blk>>>(x, xhi, xlo, TOK * EMBED / 4);         // 1
    split_transpose_kernel<<<dim3(EMBED / 32, EMBED / 32), tblk>>>(Wq, Wqkvh, Wqkvl, EMBED, EMBED);                     // 2
    split_transpose_kernel<<<dim3(EMBED / 32, EMBED / 32), tblk>>>(Wk, Wqkvh + (long)EMBED * EMBED, Wqkvl + (long)EMBED * EMBED, EMBED, EMBED); // 3
    split_transpose_kernel<<<dim3(EMBED / 32, EMBED / 32), tblk>>>(Wv, Wqkvh + 2L * EMBED * EMBED, Wqkvl + 2L * EMBED * EMBED, EMBED, EMBED);   // 4
    concat_bias_kernel<<<(NQKV + 255) / 256, blk>>>(bq, bk, bv, bqkv);                           // 5

    // 6: fused QKV = x @ [Wq|Wk|Wv] + [bq|bk|bv] -> hi/lo, ld 2304
    mma_gemm<1><<<dim3(NQKV / TILE_N, TOK / TILE_M, 1), blk, GSMEM_TOTAL>>>(
        xhi, xlo, EMBED, 0, Wqkvh, Wqkvl, EMBED, 0,
        nullptr, QKVh, QKVl, NQKV, 0, bqkv, 0.f, EMBED);

    // 7: V^T hi/lo from fused buffer
    vt_transpose_kernel<<<dim3(EMBED / 32, SEQ / 32, BATCH), tblk>>>(QKVh, QKVl, VTh, VTl);

    // 8: scores = Q @ K^T * scale (batched; Q, K are column slices of QKV)
    mma_gemm<2><<<dim3(SEQ / TILE_N, SEQ / TILE_M, BATCH), blk, GSMEM_TOTAL>>>(
        QKVh, QKVl, NQKV, (long)SEQ * NQKV,
        QKVh + EMBED, QKVl + EMBED, NQKV, (long)SEQ * NQKV,
        S, nullptr, nullptr, SEQ, (long)SEQ * SEQ, nullptr, att_scale, EMBED);
    // 9: softmax -> P hi/lo
    softmax_kernel<<<TOK, blk>>>(S, Phi, Plo);
    // 10: attn = P @ V
    mma_gemm<2><<<dim3(EMBED / TILE_N, SEQ / TILE_M, BATCH), blk, GSMEM_TOTAL>>>(
        Phi, Plo, SEQ, (long)SEQ * SEQ, VTh, VTl, SEQ, (long)EMBED * SEQ,
        attn, nullptr, nullptr, EMBED, (long)SEQ * EMBED, nullptr, 1.0f, SEQ);

    // 11: x1 = x + LN(attn) (+ split)
    ln_residual_kernel<true><<<TOK, blk>>>(x, attn, g1, beta1, x1, x1hi, x1lo);

    // 12-13: FFN1
    split_transpose_kernel<<<dim3(FF / 32, EMBED / 32), tblk>>>(W1, W1Th, W1Tl, EMBED, FF);
    mma_gemm<3><<<dim3(FF / TILE_N, TOK / TILE_M, 1), blk, GSMEM_TOTAL>>>(
        x1hi, x1lo, EMBED, 0, W1Th, W1Tl, EMBED, 0, nullptr, hhi, hlo, FF, 0, b1, 0.f, EMBED);
    // 14-15: FFN2
    split_transpose_kernel<<<dim3(EMBED / 32, FF / 32), tblk>>>(W2, W2Th, W2Tl, FF, EMBED);
    mma_gemm<0><<<dim3(EMBED / TILE_N, TOK / TILE_M, 1), blk, GSMEM_TOTAL>>>(
        hhi, hlo, FF, 0, W2Th, W2Tl, FF, 0, f, nullptr, nullptr, EMBED, 0, b2, 0.f, FF);

    // 16: out = x1 + LN(f)
    ln_residual_kernel<false><<<TOK, blk>>>(x1, f, g2, beta2, out, nullptr, nullptr);
}

// round 5
// speedup vs baseline: 3.1640x; 1.0414x over previous
#include <cuda_runtime.h>
#include <cuda_bf16.h>
#include <math.h>
#include <stdint.h>

#define EMBED 768
#define FF    3072
#define BATCH 8
#define SEQ   1024
#define TOK   (BATCH * SEQ)   // 8192
#define NQKV  (3 * EMBED)     // 2304

typedef __nv_bfloat16 bf16;

// ============================ scratch buffers ================================
__device__ __align__(16) bf16  g_xhi[TOK * EMBED],  g_xlo[TOK * EMBED];
__device__ __align__(16) bf16  g_Wqkvh[(long)NQKV * EMBED], g_Wqkvl[(long)NQKV * EMBED];
__device__ __align__(16) float g_bqkv[NQKV];
__device__ __align__(16) bf16  g_W1Th[(long)FF * EMBED], g_W1Tl[(long)FF * EMBED];
__device__ __align__(16) bf16  g_W2Th[(long)EMBED * FF], g_W2Tl[(long)EMBED * FF];
__device__ __align__(16) bf16  g_QKVh[(long)TOK * NQKV], g_QKVl[(long)TOK * NQKV];
__device__ __align__(16) bf16  g_VTh[(long)BATCH * EMBED * SEQ], g_VTl[(long)BATCH * EMBED * SEQ];
__device__ __align__(16) float g_S[(long)BATCH * SEQ * SEQ];
__device__ __align__(16) bf16  g_Phi[(long)BATCH * SEQ * SEQ], g_Plo[(long)BATCH * SEQ * SEQ];
__device__ __align__(16) float g_attnP[2L * TOK * EMBED];          // PV split-K partials
__device__ __align__(16) float g_x1[TOK * EMBED];
__device__ __align__(16) bf16  g_x1hi[TOK * EMBED], g_x1lo[TOK * EMBED];
__device__ __align__(16) bf16  g_hhi[(long)TOK * FF], g_hlo[(long)TOK * FF];
__device__ __align__(16) float g_fP[3L * TOK * EMBED];             // FFN2 split-K partials

// ============================ PTX helpers ====================================
__device__ __forceinline__ uint32_t smem_u32(const void* p) {
    uint32_t a;
    asm("{ .reg .u64 t; cvta.to.shared.u64 t, %1; cvt.u32.u64 %0, t; }" : "=r"(a) : "l"(p));
    return a;
}
__device__ __forceinline__ void cp16(uint32_t dst, const void* src) {
    asm volatile("cp.async.cg.shared.global [%0], [%1], 16;" :: "r"(dst), "l"(src));
}
#define CP_COMMIT() asm volatile("cp.async.commit_group;" ::: "memory")

__device__ __forceinline__ void ldm_x4(uint32_t* r, uint32_t addr) {
    asm volatile("ldmatrix.sync.aligned.m8n8.x4.shared.b16 {%0,%1,%2,%3}, [%4];"
                 : "=r"(r[0]), "=r"(r[1]), "=r"(r[2]), "=r"(r[3]) : "r"(addr));
}
__device__ __forceinline__ void mma16816(float* d, const uint32_t* a, uint32_t b0, uint32_t b1) {
    asm volatile(
        "mma.sync.aligned.m16n8k16.row.col.f32.bf16.bf16.f32 "
        "{%0,%1,%2,%3}, {%4,%5,%6,%7}, {%8,%9}, {%0,%1,%2,%3};"
        : "+f"(d[0]), "+f"(d[1]), "+f"(d[2]), "+f"(d[3])
        : "r"(a[0]), "r"(a[1]), "r"(a[2]), "r"(a[3]), "r"(b0), "r"(b1));
}
#define SWZ128(o) ((o) ^ (((o) >> 3) & 0x70))

__device__ __forceinline__ float gelu_exact(float v) {
    return 0.5f * v * (1.0f + erff(v * 0.7071067811865475f));
}

// ============================ big-tile mma GEMM ==============================
// C[M,N] = (Ahi+Alo)[M,K] @ (Bhi+Blo)[N,K]^T   (both K-major row-major)
// CTA tile 256x128, warp tile 64x64 (8 warps: 4M x 2N), BK=64, 2-stage pipe.
// blockIdx.z = batch*ksplit + split;  K = per-split K length.
// EPI: 0 bias->fp32 | 1 bias->(hi,lo) | 2 scale->fp32 | 3 bias+gelu->(hi,lo)
#define BT_M 256
#define BT_N 128
#define BK   64
#define BSTAGE 98304            // Ah 32K | Al 32K | Bh 16K | Bl 16K
#define BSMEM_TOTAL (2 * BSTAGE)

template <int EPI>
__global__ __launch_bounds__(256, 1)
void mma_gemm_big(const bf16* __restrict__ Ahi, const bf16* __restrict__ Alo, long ldA, long bsA,
                  const bf16* __restrict__ Bhi, const bf16* __restrict__ Blo, long ldB, long bsB,
                  float* __restrict__ C, bf16* __restrict__ Chi, bf16* __restrict__ Clo,
                  long ldC, long bsC, const float* __restrict__ bias, float scale, int K,
                  int ksplit, long spStrideC)
{
    extern __shared__ char smem[];
    const uint32_t sbase = smem_u32(smem);
    const int tid  = threadIdx.x;
    const int bz   = blockIdx.z;
    const int sp   = bz % ksplit;
    const int bt   = bz / ksplit;
    const long koff = (long)sp * K;
    const int row0 = blockIdx.y * BT_M;
    const int col0 = blockIdx.x * BT_N;

    const bf16* Ah = Ahi + (long)bt * bsA + koff;
    const bf16* Al = Alo + (long)bt * bsA + koff;
    const bf16* Bh = Bhi + (long)bt * bsB + koff;
    const bf16* Bl = Blo + (long)bt * bsB + koff;

    const int NC = K / BK;

    auto load_stage = [&](int buf, int k0) {
        const uint32_t sb = sbase + (uint32_t)buf * BSTAGE;
        #pragma unroll
        for (int i = 0; i < 8; i++) {            // A: 2048 granules per type
            const int g = tid + 256 * i;
            const int r = g >> 3, c = g & 7;
            const uint32_t off = SWZ128((uint32_t)(r * 128 + c * 16));
            const long ai = (long)(row0 + r) * ldA + k0 + c * 8;
            cp16(sb + off,         Ah + ai);
            cp16(sb + 32768 + off, Al + ai);
        }
        #pragma unroll
        for (int i = 0; i < 4; i++) {            // B: 1024 granules per type
            const int g = tid + 256 * i;
            const int r = g >> 3, c = g & 7;
            const uint32_t off = SWZ128((uint32_t)(r * 128 + c * 16));
            const long bi = (long)(col0 + r) * ldB + k0 + c * 8;
            cp16(sb + 65536 + off, Bh + bi);
            cp16(sb + 81920 + off, Bl + bi);
        }
    };

    load_stage(0, 0);
    CP_COMMIT();
    if (NC > 1) { load_stage(1, BK); CP_COMMIT(); }

    const int w    = tid >> 5;
    const int lane = tid & 31;
    const int wm   = w & 3;            // rows wm*64
    const int wn   = w >> 2;           // cols wn*64
    const int q    = lane >> 3;
    const int r8   = lane & 7;

    float acc[4][8][4];
    #pragma unroll
    for (int i = 0; i < 4; i++)
        #pragma unroll
        for (int j = 0; j < 8; j++)
            #pragma unroll
            for (int v = 0; v < 4; v++) acc[i][j][v] = 0.0f;

    for (int c = 0; c < NC; c++) {
        if (c + 1 < NC) asm volatile("cp.async.wait_group 1;" ::: "memory");
        else            asm volatile("cp.async.wait_group 0;" ::: "memory");
        __syncthreads();

        const uint32_t sb = sbase + (uint32_t)(c & 1) * BSTAGE;
        #pragma unroll
        for (int ks = 0; ks < 4; ks++) {
            uint32_t bhf[4][4], blf[4][4];
            #pragma unroll
            for (int p = 0; p < 4; p++) {
                const int nn = wn * 64 + p * 16 + (q >> 1) * 8 + r8;
                const int cc = 2 * ks + (q & 1);
                const uint32_t off = SWZ128((uint32_t)(nn * 128 + cc * 16));
                ldm_x4(bhf[p], sb + 65536 + off);
                ldm_x4(blf[p], sb + 81920 + off);
            }
            #pragma unroll
            for (int am = 0; am < 4; am++) {
                uint32_t ah[4], al[4];
                const int rr = wm * 64 + am * 16 + (q & 1) * 8 + r8;
                const int cc = 2 * ks + (q >> 1);
                const uint32_t off = SWZ128((uint32_t)(rr * 128 + cc * 16));
                ldm_x4(ah, sb + off);
                ldm_x4(al, sb + 32768 + off);
                #pragma unroll
                for (int bn = 0; bn < 8; bn++) {
                    const int p = bn >> 1, hf = (bn & 1) * 2;
                    mma16816(acc[am][bn], ah, bhf[p][hf], bhf[p][hf + 1]);
                    mma16816(acc[am][bn], al, bhf[p][hf], bhf[p][hf + 1]);
                    mma16816(acc[am][bn], ah, blf[p][hf], blf[p][hf + 1]);
                }
            }
        }
        __syncthreads();
        if (c + 2 < NC) {
            load_stage(c & 1, (c + 2) * BK);
            CP_COMMIT();
        }
    }

    // -------- epilogue --------
    const int gg = lane >> 2, t = lane & 3;
    float* Cp = (EPI == 0 || EPI == 2) ? C + (long)bt * bsC + (long)sp * spStrideC : nullptr;
    bf16* Hp  = (EPI == 1 || EPI == 3) ? Chi + (long)bt * bsC : nullptr;
    bf16* Lp  = (EPI == 1 || EPI == 3) ? Clo + (long)bt * bsC : nullptr;

    #pragma unroll
    for (int am = 0; am < 4; am++) {
        const long r0 = row0 + wm * 64 + am * 16 + gg;
        const long r1 = r0 + 8;
        #pragma unroll
        for (int bn = 0; bn < 8; bn++) {
            const int col = col0 + wn * 64 + bn * 8 + 2 * t;
            float v[4];
            #pragma unroll
            for (int i = 0; i < 4; i++) v[i] = acc[am][bn][i];
            if (EPI == 2) {
                #pragma unroll
                for (int i = 0; i < 4; i++) v[i] *= scale;
            } else {
                const float b0 = __ldg(&bias[col]);
                const float b1 = __ldg(&bias[col + 1]);
                v[0] += b0; v[1] += b1; v[2] += b0; v[3] += b1;
                if (EPI == 3) {
                    #pragma unroll
                    for (int i = 0; i < 4; i++) v[i] = gelu_exact(v[i]);
                }
            }
            if (EPI == 0 || EPI == 2) {
                *(float2*)(Cp + r0 * ldC + col) = make_float2(v[0], v[1]);
                *(float2*)(Cp + r1 * ldC + col) = make_float2(v[2], v[3]);
            } else {
                bf16 a0 = __float2bfloat16(v[0]), a1 = __float2bfloat16(v[1]);
                bf16 a2 = __float2bfloat16(v[2]), a3 = __float2bfloat16(v[3]);
                *(ushort2*)(Hp + r0 * ldC + col) =
                    make_ushort2(__bfloat16_as_ushort(a0), __bfloat16_as_ushort(a1));
                *(ushort2*)(Hp + r1 * ldC + col) =
                    make_ushort2(__bfloat16_as_ushort(a2), __bfloat16_as_ushort(a3));
                *(ushort2*)(Lp + r0 * ldC + col) = make_ushort2(
                    __bfloat16_as_ushort(__float2bfloat16(v[0] - __bfloat162float(a0))),
                    __bfloat16_as_ushort(__float2bfloat16(v[1] - __bfloat162float(a1))));
                *(ushort2*)(Lp + r1 * ldC + col) = make_ushort2(
                    __bfloat16_as_ushort(__float2bfloat16(v[2] - __bfloat162float(a2))),
                    __bfloat16_as_ushort(__float2bfloat16(v[3] - __bfloat162float(a3))));
            }
        }
    }
}

// ============================ glue kernels ===================================
__global__ __launch_bounds__(256)
void split_kernel(const float* __restrict__ in, bf16* __restrict__ hi, bf16* __restrict__ lo, long n4)
{
    long i = (long)blockIdx.x * blockDim.x + threadIdx.x;
    if (i >= n4) return;
    float4 v = ((const float4*)in)[i];
    unsigned short h[4], l[4];
    float vv[4] = {v.x, v.y, v.z, v.w};
    #pragma unroll
    for (int j = 0; j < 4; j++) {
        bf16 hb = __float2bfloat16(vv[j]);
        h[j] = __bfloat16_as_ushort(hb);
        l[j] = __bfloat16_as_ushort(__float2bfloat16(vv[j] - __bfloat162float(hb)));
    }
    ((uint2*)hi)[i] = *(uint2*)h;
    ((uint2*)lo)[i] = *(uint2*)l;
}

// One launch: transpose+split all 5 weights [R,C]->[C,R] hi/lo, plus bias concat.
__global__ __launch_bounds__(256)
void mega_wsplit(const float* __restrict__ Wq, const float* __restrict__ Wk,
                 const float* __restrict__ Wv, const float* __restrict__ W1,
                 const float* __restrict__ W2,
                 const float* __restrict__ bq, const float* __restrict__ bk,
                 const float* __restrict__ bv,
                 bf16* __restrict__ Wqkvh, bf16* __restrict__ Wqkvl,
                 bf16* __restrict__ W1h, bf16* __restrict__ W1l,
                 bf16* __restrict__ W2h, bf16* __restrict__ W2l,
                 float* __restrict__ bqkv)
{
    const int tflat = threadIdx.y * 32 + threadIdx.x;
    const int blk = blockIdx.x;
    if (blk == 6336) {                      // bias concat
        for (int i = tflat; i < NQKV; i += 256)
            bqkv[i] = (i < EMBED) ? bq[i] : (i < 2 * EMBED) ? bk[i - EMBED] : bv[i - 2 * EMBED];
        return;
    }
    const float* in; bf16 *hi, *lo;
    int R, C, bx, by;
    if (blk < 1728) {
        const int ww = blk / 576, loc = blk % 576;
        in = (ww == 0) ? Wq : (ww == 1) ? Wk : Wv;
        hi = g_Wqkvh + (long)ww * EMBED * EMBED;
        lo = g_Wqkvl + (long)ww * EMBED * EMBED;
        (void)Wqkvh; (void)Wqkvl;
        R = EMBED; C = EMBED; bx = loc % 24; by = loc / 24;
    } else if (blk < 4032) {
        const int loc = blk - 1728;
        in = W1; hi = W1h; lo = W1l;
        R = EMBED; C = FF; bx = loc % 96; by = loc / 96;
    } else {
        const int loc = blk - 4032;
        in = W2; hi = W2h; lo = W2l;
        R = FF; C = EMBED; bx = loc % 24; by = loc / 24;
    }
    __shared__ float tshr[32][33];
    const int tx = threadIdx.x, ty = threadIdx.y;
    const int c = bx * 32 + tx;
    const int r0 = by * 32;
    #pragma unroll
    for (int i = 0; i < 4; i++)
        tshr[ty + i * 8][tx] = in[(long)(r0 + ty + i * 8) * C + c];
    __syncthreads();
    const int co0 = bx * 32;
    #pragma unroll
    for (int i = 0; i < 4; i++) {
        float v = tshr[tx][ty + i * 8];
        bf16 h = __float2bfloat16(v);
        long o = (long)(co0 + ty + i * 8) * R + r0 + tx;
        hi[o] = h;
        lo[o] = __float2bfloat16(v - __bfloat162float(h));
    }
}

// V slice of fused QKV (hi+lo, ld=NQKV) -> VT hi/lo [B, EMBED, SEQ]
__global__ __launch_bounds__(256)
void vt_transpose_kernel(const bf16* __restrict__ hi_in, const bf16* __restrict__ lo_in,
                         bf16* __restrict__ hiT, bf16* __restrict__ loT)
{
    __shared__ float t[32][33];
    const int tx = threadIdx.x, ty = threadIdx.y;
    const long b = blockIdx.z;
    const int e = blockIdx.x * 32 + tx;
    const int s0 = blockIdx.y * 32;
    const long ib = b * SEQ;
    #pragma unroll
    for (int i = 0; i < 4; i++) {
        const long idx = (ib + s0 + ty + i * 8) * NQKV + 2 * EMBED + e;
        t[ty + i * 8][tx] = __bfloat162float(hi_in[idx]) + __bfloat162float(lo_in[idx]);
    }
    __syncthreads();
    const int e0 = blockIdx.x * 32;
    #pragma unroll
    for (int i = 0; i < 4; i++) {
        float v = t[tx][ty + i * 8];
        bf16 h = __float2bfloat16(v);
        const long o = b * EMBED * SEQ + (long)(e0 + ty + i * 8) * SEQ + s0 + tx;
        hiT[o] = h;
        loT[o] = __float2bfloat16(v - __bfloat162float(h));
    }
}

__global__ __launch_bounds__(256)
void softmax_kernel(float* __restrict__ S, bf16* __restrict__ Phi, bf16* __restrict__ Plo)
{
    float* row = S + (long)blockIdx.x * SEQ;
    const int tid = threadIdx.x;
    float v[4];
    float m = -1e30f;
    #pragma unroll
    for (int j = 0; j < 4; j++) { v[j] = row[tid + 256 * j]; m = fmaxf(m, v[j]); }
    __shared__ float red[8];
    #pragma unroll
    for (int o = 16; o > 0; o >>= 1) m = fmaxf(m, __shfl_xor_sync(0xffffffffu, m, o));
    if ((tid & 31) == 0) red[tid >> 5] = m;
    __syncthreads();
    m = red[0];
    #pragma unroll
    for (int i = 1; i < 8; i++) m = fmaxf(m, red[i]);
    float s = 0.0f;
    #pragma unroll
    for (int j = 0; j < 4; j++) { v[j] = __expf(v[j] - m); s += v[j]; }
    __syncthreads();
    #pragma unroll
    for (int o = 16; o > 0; o >>= 1) s += __shfl_xor_sync(0xffffffffu, s, o);
    if ((tid & 31) == 0) red[tid >> 5] = s;
    __syncthreads();
    s = 0.0f;
    #pragma unroll
    for (int i = 0; i < 8; i++) s += red[i];
    const float inv = 1.0f / s;
    bf16* ph = Phi + (long)blockIdx.x * SEQ;
    bf16* pl = Plo + (long)blockIdx.x * SEQ;
    #pragma unroll
    for (int j = 0; j < 4; j++) {
        float p = v[j] * inv;
        bf16 h = __float2bfloat16(p);
        ph[tid + 256 * j] = h;
        pl[tid + 256 * j] = __float2bfloat16(p - __bfloat162float(h));
    }
}

// out = xin + LN(t0 (+t1) (+t2) (+bias)) * g + beta;  optional hi/lo split out.
template <int NT, bool HASB, bool SPLIT>
__global__ __launch_bounds__(256)
void ln_residual_kernel(const float* __restrict__ xin,
                        const float* __restrict__ t0, const float* __restrict__ t1,
                        const float* __restrict__ t2, const float* __restrict__ bvec,
                        const float* __restrict__ g, const float* __restrict__ beta,
                        float* __restrict__ out, bf16* __restrict__ ohi, bf16* __restrict__ olo)
{
    const long base = (long)blockIdx.x * EMBED;
    const int tid = threadIdx.x;
    float vv[3];
    #pragma unroll
    for (int j = 0; j < 3; j++) {
        const int o = tid + j * 256;
        float v = t0[base + o];
        if (NT >= 2) v += t1[base + o];
        if (NT >= 3) v += t2[base + o];
        if (HASB)    v += bvec[o];
        vv[j] = v;
    }
    float s = vv[0] + vv[1] + vv[2];
    float q = vv[0] * vv[0] + vv[1] * vv[1] + vv[2] * vv[2];
    __shared__ float rs[8], rq[8];
    #pragma unroll
    for (int o = 16; o > 0; o >>= 1) {
        s += __shfl_xor_sync(0xffffffffu, s, o);
        q += __shfl_xor_sync(0xffffffffu, q, o);
    }
    if ((tid & 31) == 0) { rs[tid >> 5] = s; rq[tid >> 5] = q; }
    __syncthreads();
    s = 0.0f; q = 0.0f;
    #pragma unroll
    for (int i = 0; i < 8; i++) { s += rs[i]; q += rq[i]; }
    const float mu  = s * (1.0f / EMBED);
    const float var = q * (1.0f / EMBED) - mu * mu;
    const float inv = rsqrtf(var + 1e-5f);
    #pragma unroll
    for (int j = 0; j < 3; j++) {
        const int o = tid + j * 256;
        float r = xin[base + o] + (vv[j] - mu) * inv * g[o] + beta[o];
        out[base + o] = r;
        if (SPLIT) {
            bf16 h = __float2bfloat16(r);
            ohi[base + o] = h;
            olo[base + o] = __float2bfloat16(r - __bfloat162float(h));
        }
    }
}

// ============================ launcher =======================================
extern "C" void kernel_launch(void* const* d_in, const int* in_sizes, int n_in,
                              void* d_out, int out_size)
{
    const float* x     = (const float*)d_in[0];
    const float* Wq    = (const float*)d_in[1];
    const float* bq    = (const float*)d_in[2];
    const float* Wk    = (const float*)d_in[3];
    const float* bk    = (const float*)d_in[4];
    const float* Wv    = (const float*)d_in[5];
    const float* bv    = (const float*)d_in[6];
    const float* W1    = (const float*)d_in[7];
    const float* b1    = (const float*)d_in[8];
    const float* W2    = (const float*)d_in[9];
    const float* b2    = (const float*)d_in[10];
    const float* g1    = (const float*)d_in[11];
    const float* beta1 = (const float*)d_in[12];
    const float* g2    = (const float*)d_in[13];
    const float* beta2 = (const float*)d_in[14];
    float* out = (float*)d_out;

    bf16 *xhi, *xlo, *Wqkvh, *Wqkvl, *W1Th, *W1Tl, *W2Th, *W2Tl;
    bf16 *QKVh, *QKVl, *VTh, *VTl, *Phi, *Plo, *x1hi, *x1lo, *hhi, *hlo;
    float *bqkv, *S, *attnP, *x1, *fP;
    cudaGetSymbolAddress((void**)&xhi, g_xhi);     cudaGetSymbolAddress((void**)&xlo, g_xlo);
    cudaGetSymbolAddress((void**)&Wqkvh, g_Wqkvh); cudaGetSymbolAddress((void**)&Wqkvl, g_Wqkvl);
    cudaGetSymbolAddress((void**)&bqkv, g_bqkv);
    cudaGetSymbolAddress((void**)&W1Th, g_W1Th);   cudaGetSymbolAddress((void**)&W1Tl, g_W1Tl);
    cudaGetSymbolAddress((void**)&W2Th, g_W2Th);   cudaGetSymbolAddress((void**)&W2Tl, g_W2Tl);
    cudaGetSymbolAddress((void**)&QKVh, g_QKVh);   cudaGetSymbolAddress((void**)&QKVl, g_QKVl);
    cudaGetSymbolAddress((void**)&VTh, g_VTh);     cudaGetSymbolAddress((void**)&VTl, g_VTl);
    cudaGetSymbolAddress((void**)&S, g_S);
    cudaGetSymbolAddress((void**)&Phi, g_Phi);     cudaGetSymbolAddress((void**)&Plo, g_Plo);
    cudaGetSymbolAddress((void**)&attnP, g_attnP);
    cudaGetSymbolAddress((void**)&x1, g_x1);
    cudaGetSymbolAddress((void**)&x1hi, g_x1hi);   cudaGetSymbolAddress((void**)&x1lo, g_x1lo);
    cudaGetSymbolAddress((void**)&hhi, g_hhi);     cudaGetSymbolAddress((void**)&hlo, g_hlo);
    cudaGetSymbolAddress((void**)&fP, g_fP);

    cudaFuncSetAttribute(mma_gemm_big<0>, cudaFuncAttributeMaxDynamicSharedMemorySize, BSMEM_TOTAL);
    cudaFuncSetAttribute(mma_gemm_big<1>, cudaFuncAttributeMaxDynamicSharedMemorySize, BSMEM_TOTAL);
    cudaFuncSetAttribute(mma_gemm_big<2>, cudaFuncAttributeMaxDynamicSharedMemorySize, BSMEM_TOTAL);
    cudaFuncSetAttribute(mma_gemm_big<3>, cudaFuncAttributeMaxDynamicSharedMemorySize, BSMEM_TOTAL);

    const dim3 blk(256);
    const dim3 tblk(32, 8);
    const float att_scale = 1.0f / sqrtf((float)EMBED);

    // 0: split x -> hi/lo
    split_kernel<<<(TOK * EMBED / 4 + 255) / 256, blk>>>(x, xhi, xlo, TOK * EMBED / 4);
    // 1: all weight splits + bias concat (single launch)
    mega_wsplit<<<6337, tblk>>>(Wq, Wk, Wv, W1, W2, bq, bk, bv,
                                Wqkvh, Wqkvl, W1Th, W1Tl, W2Th, W2Tl, bqkv);
    // 2: fused QKV = x @ [Wq|Wk|Wv] + bias -> hi/lo
    mma_gemm_big<1><<<dim3(NQKV / BT_N, TOK / BT_M, 1), blk, BSMEM_TOTAL>>>(
        xhi, xlo, EMBED, 0, Wqkvh, Wqkvl, EMBED, 0,
        nullptr, QKVh, QKVl, NQKV, 0, bqkv, 0.f, EMBED, 1, 0);
    // 3: V^T hi/lo
    vt_transpose_kernel<<<dim3(EMBED / 32, SEQ / 32, BATCH), tblk>>>(QKVh, QKVl, VTh, VTl);
    // 4: scores = Q @ K^T * scale  (256 CTAs)
    mma_gemm_big<2><<<dim3(SEQ / BT_N, SEQ / BT_M, BATCH), blk, BSMEM_TOTAL>>>(
        QKVh, QKVl, NQKV, (long)SEQ * NQKV,
        QKVh + EMBED, QKVl + EMBED, NQKV, (long)SEQ * NQKV,
        S, nullptr, nullptr, SEQ, (long)SEQ * SEQ, nullptr, att_scale, EMBED, 1, 0);
    // 5: softmax -> P hi/lo
    softmax_kernel<<<TOK, blk>>>(S, Phi, Plo);
    // 6: attn partials = P @ V, split-K=2 (z = batch*2)
    mma_gemm_big<2><<<dim3(EMBED / BT_N, SEQ / BT_M, BATCH * 2), blk, BSMEM_TOTAL>>>(
        Phi, Plo, SEQ, (long)SEQ * SEQ, VTh, VTl, SEQ, (long)EMBED * SEQ,
        attnP, nullptr, nullptr, EMBED, (long)SEQ * EMBED, nullptr, 1.0f, SEQ / 2,
        2, (long)TOK * EMBED);
    // 7: x1 = x + LN(attn0 + attn1)  (+ split)
    ln_residual_kernel<2, false, true><<<TOK, blk>>>(
        x, attnP, attnP + (long)TOK * EMBED, nullptr, nullptr, g1, beta1, x1, x1hi, x1lo);
    // 8: h = gelu(x1 @ W1 + b1) -> hi/lo
    mma_gemm_big<3><<<dim3(FF / BT_N, TOK / BT_M, 1), blk, BSMEM_TOTAL>>>(
        x1hi, x1lo, EMBED, 0, W1Th, W1Tl, EMBED, 0,
        nullptr, hhi, hlo, FF, 0, b1, 0.f, EMBED, 1, 0);
    // 9: f partials = h @ W2, split-K=3
    mma_gemm_big<2><<<dim3(EMBED / BT_N, TOK / BT_M, 3), blk, BSMEM_TOTAL>>>(
        hhi, hlo, FF, 0, W2Th, W2Tl, FF, 0,
        fP, nullptr, nullptr, EMBED, 0, nullptr, 1.0f, FF / 3, 3, (long)TOK * EMBED);
    // 10: out = x1 + LN(f0+f1+f2 + b2)
    ln_residual_kernel<3, true, false><<<TOK, blk>>>(
        x1, fP, fP + (long)TOK * EMBED, fP + 2L * TOK * EMBED, b2, g2, beta2,
        out, nullptr, nullptr);
}